// round 10
// baseline (speedup 1.0000x reference)
#include <cuda_runtime.h>
#include <math.h>

// ---------------- problem constants ----------------
#define N_DIM 121
#define K_RAW 242            // stacked K = 2*N
#define K_PAD 244            // padded to /4 (float4)
#define K4    61             // K_PAD/4
#define NPAD  128
#define BM    96             // rows per block
#define B_MAX 32768

// g scratch (sigmoid outputs), real/imag planes. __device__ global = allowed scratch.
__device__ float g_scratch[2][B_MAX * N_DIM];

// ---------------- packed f32x2 helpers ----------------
__device__ __forceinline__ unsigned long long pk2(float lo, float hi) {
    unsigned long long r;
    asm("mov.b64 %0, {%1, %2};" : "=l"(r) : "f"(lo), "f"(hi));
    return r;
}
__device__ __forceinline__ void upk2(unsigned long long v, float& lo, float& hi) {
    asm("mov.b64 {%0, %1}, %2;" : "=f"(lo), "=f"(hi) : "l"(v));
}
__device__ __forceinline__ void fma2(unsigned long long& acc, unsigned long long a,
                                     unsigned long long b) {
    asm("fma.rn.f32x2 %0, %1, %2, %0;" : "+l"(acc) : "l"(a), "l"(b));
}

__device__ __forceinline__ float safe_ld(const float* p, long long idx, long long sz) {
    return (p != nullptr && idx >= 0 && idx < sz) ? p[idx] : 0.f;
}

// ---------------- GEMM + sigmoid kernel (full-K resident smem) ----------------
// g[b,n] = sigmoid( sum_k z[b,k]*W[n,k] + sum_k v[b,k]*U[n,k] + bW[n] + bU[n] )
// blockIdx.y: 0 = real plane, 1 = imag plane.
// smem: Ws[128][244] + As[96][244] + bias[128] = 219,648 B dynamic.
#define SMEM_FLOATS (NPAD * K_PAD + BM * K_PAD + NPAD)
#define SMEM_BYTES  (SMEM_FLOATS * 4)

extern "C" __global__ void __launch_bounds__(256, 1)
gate_gemm_kernel(const float* __restrict__ z_r, const float* __restrict__ v_r,
                 const float* __restrict__ Wr,  const float* __restrict__ Wrb,
                 const float* __restrict__ Ur,  const float* __restrict__ Urb,
                 const float* __restrict__ z_i, const float* __restrict__ v_i,
                 const float* __restrict__ Wi,  const float* __restrict__ Wib,
                 const float* __restrict__ Ui,  const float* __restrict__ Uib,
                 long long sz_zv, long long sz_w, long long sz_b, int Brows)
{
    extern __shared__ float smem[];
    float* Ws = smem;                     // [128][244]
    float* As = smem + NPAD * K_PAD;      // [96][244]
    float* Bs = As + BM * K_PAD;          // [128]

    const int part = blockIdx.y;
    const float* Z  = part ? z_i : z_r;
    const float* V  = part ? v_i : v_r;
    const float* W  = part ? Wi  : Wr;
    const float* U  = part ? Ui  : Ur;
    const float* Wb = part ? Wib : Wrb;
    const float* Ub = part ? Uib : Urb;

    const int tid  = threadIdx.x;
    const int row0 = blockIdx.x * BM;

    // --- load full concatenated weights [n][k] = W[n,k] | U[n,k-121] | 0 ---
    for (int idx = tid; idx < NPAD * K_PAD; idx += 256) {
        int n = idx / K_PAD;
        int k = idx - n * K_PAD;
        float val = 0.f;
        if (n < N_DIM) {
            if (k < N_DIM)      val = safe_ld(W, (long long)n * N_DIM + k, sz_w);
            else if (k < K_RAW) val = safe_ld(U, (long long)n * N_DIM + (k - N_DIM), sz_w);
        }
        Ws[idx] = val;
    }
    // --- load full A tile [r][k] = z[row,k] | v[row,k-121] | 0 ---
    for (int idx = tid; idx < BM * K_PAD; idx += 256) {
        int r = idx / K_PAD;
        int k = idx - r * K_PAD;
        long long row = row0 + r;
        float val = 0.f;
        if (row < Brows) {
            if (k < N_DIM)      val = safe_ld(Z, row * N_DIM + k, sz_zv);
            else if (k < K_RAW) val = safe_ld(V, row * N_DIM + (k - N_DIM), sz_zv);
        }
        As[idx] = val;
    }
    if (tid < NPAD)
        Bs[tid] = (tid < N_DIM)
                    ? (safe_ld(Wb, tid, sz_b) + safe_ld(Ub, tid, sz_b)) : 0.f;
    __syncthreads();

    // warp layout: 8 warps x 12 rows = 96 rows; lane = 16*rg + cg
    const int lane = tid & 31;
    const int warp = tid >> 5;
    const int cg   = lane & 15;         // n = cg + 16*j, j=0..7
    const int rg   = lane >> 4;         // row group within warp
    const int rb   = warp * 12 + rg * 6; // thread's first row (6 rows)

    const float4* Ws4 = reinterpret_cast<const float4*>(Ws);
    const float4* As4 = reinterpret_cast<const float4*>(As);

    // k-packed f32x2 accumulators: 6 rows x 8 cols
    unsigned long long acc[6][8];
#pragma unroll
    for (int r = 0; r < 6; ++r)
#pragma unroll
        for (int j = 0; j < 8; ++j) acc[r][j] = 0ull;

    for (int kk = 0; kk < K4; ++kk) {
        unsigned long long a01[6], a23[6];
#pragma unroll
        for (int r = 0; r < 6; ++r) {
            float4 a4 = As4[(rb + r) * K4 + kk];   // 16-lane broadcast
            a01[r] = pk2(a4.x, a4.y);
            a23[r] = pk2(a4.z, a4.w);
        }
#pragma unroll
        for (int j = 0; j < 8; ++j) {
            float4 w4 = Ws4[(cg + 16 * j) * K4 + kk];  // conflict-free
            unsigned long long w01 = pk2(w4.x, w4.y);
            unsigned long long w23 = pk2(w4.z, w4.w);
#pragma unroll
            for (int r = 0; r < 6; ++r) {
                fma2(acc[r][j], a01[r], w01);
                fma2(acc[r][j], a23[r], w23);
            }
        }
    }

    // epilogue: horizontal add + bias + sigmoid -> g_scratch
    float* gdst = g_scratch[part];
#pragma unroll
    for (int r = 0; r < 6; ++r) {
        long long row = row0 + rb + r;
        if (row >= Brows) continue;
#pragma unroll
        for (int j = 0; j < 8; ++j) {
            int n = cg + 16 * j;
            if (n < N_DIM) {
                float lo, hi;
                upk2(acc[r][j], lo, hi);
                float t = lo + hi + Bs[n];
                gdst[row * N_DIM + n] = 1.f / (1.f + __expf(-t));
            }
        }
    }
}

// ---------------- fused complex epilogue kernel ----------------
// x = (A_H_y + eta*(z-v)) / (w + eta);  u = x + v
// zo = g*u + (1-g)*z;  vo = v + x - zo
// Output: six BN-float planes: [x_re][z_re][v_re][x_im][z_im][v_im]
extern "C" __global__ void __launch_bounds__(256)
fuse_kernel(const float* __restrict__ ayr, const float* __restrict__ ayi,
            const float* __restrict__ zr,  const float* __restrict__ zi,
            const float* __restrict__ vr,  const float* __restrict__ vi,
            const float* __restrict__ wdr, const float* __restrict__ wdi,
            const float* __restrict__ raw_eta,
            float* __restrict__ out, int BN,
            long long sz_eta, long long out_floats)
{
    int idx = blockIdx.x * blockDim.x + threadIdx.x;
    if (idx >= BN) return;

    float re  = safe_ld(raw_eta, 0, sz_eta);
    float eta = fmaxf(re, 0.f) + log1pf(__expf(-fabsf(re)));

    int n = idx % N_DIM;   // compiler strength-reduces constant modulo

    float zpr = zr[idx], zpi = zi[idx];
    float vpr = vr[idx], vpi = vi[idx];

    float nr = ayr[idx] + eta * (zpr - vpr);
    float ni = ayi[idx] + eta * (zpi - vpi);
    float dr = wdr[n] + eta;
    float di = wdi[n];
    float inv = 1.f / (dr * dr + di * di);
    float xr = (nr * dr + ni * di) * inv;
    float xi = (ni * dr - nr * di) * inv;

    float ur = xr + vpr;
    float ui = xi + vpi;

    float gr = g_scratch[0][idx];
    float gi = g_scratch[1][idx];

    float zor = gr * ur - gi * ui + (1.f - gr) * zpr + gi * zpi;
    float zoi = gr * ui + gi * ur + (1.f - gr) * zpi - gi * zpr;

    float vor = vpr + xr - zor;
    float voi = vpi + xi - zoi;

    // plane order: x_re, z_re, v_re, x_im, z_im, v_im (stores guarded)
    float res[6] = {xr, zor, vor, xi, zoi, voi};
#pragma unroll
    for (int p = 0; p < 6; ++p) {
        long long fi = (long long)p * BN + idx;
        if (fi < out_floats) out[fi] = res[p];
    }
}

// ---------------- launch ----------------
extern "C" void kernel_launch(void* const* d_in, const int* in_sizes, int n_in,
                              void* d_out, int out_size)
{
    const float* P[17];
    long long    S[17];
    for (int i = 0; i < 17; ++i) {
        P[i] = (i < n_in) ? (const float*)d_in[i] : nullptr;
        S[i] = (i < n_in) ? (long long)in_sizes[i] : 0;
    }
    const float *ayr = P[0],  *ayi = P[1];
    const float *zr  = P[2],  *zi  = P[3];
    const float *vr  = P[4],  *vi  = P[5];
    const float *wdr = P[6],  *wdi = P[7];
    const float *reta= P[8];
    const float *Wrw = P[9],  *Wrb = P[10];
    const float *Urw = P[11], *Urb = P[12];
    const float *Wiw = P[13], *Wib = P[14];
    const float *Uiw = P[15], *Uib = P[16];

    long long BNl = S[0];
    if (BNl > (long long)B_MAX * N_DIM) BNl = (long long)B_MAX * N_DIM;
    int BN = (int)BNl;
    int B  = BN / N_DIM;
    if (B < 1) B = 1;

    cudaFuncSetAttribute(gate_gemm_kernel,
                         cudaFuncAttributeMaxDynamicSharedMemorySize, SMEM_BYTES);

    dim3 ggrid((B + BM - 1) / BM, 2);
    gate_gemm_kernel<<<ggrid, 256, SMEM_BYTES>>>(
        zr, vr, Wrw, Wrb, Urw, Urb,
        zi, vi, Wiw, Wib, Uiw, Uib,
        S[2], S[9], S[10], B);

    int fblocks = (BN + 255) / 256;
    fuse_kernel<<<fblocks, 256>>>(ayr, ayi, zr, zi, vr, vi, wdr, wdi, reta,
                                  (float*)d_out, BN,
                                  S[8], (long long)out_size);
}